// round 3
// baseline (speedup 1.0000x reference)
#include <cuda_runtime.h>
#include <math.h>

#define BATCH 512
#define DIM   65536
#define NWIN  13

// scratch: per batch b: slots 0..12 = raw quadratic forms, slot 13 = ||x||^2
__device__ float g_Q[BATCH * 16];
// coef[i*16+j] = (i==j ? A_ii : 2*A_ij) for j>=i else 0
__device__ float g_coef[256];

// ---------------------------------------------------------------------------
// Setup: build A = Re(U^H (X^{ox4}) U) in fp64. 1 block x 256 threads.
// ---------------------------------------------------------------------------
struct cplx { double re, im; };
__device__ __forceinline__ cplx cmul(cplx a, cplx b) {
    return { a.re*b.re - a.im*b.im, a.re*b.im + a.im*b.re };
}

// inverse permutation of ring_of_cnot(4); qubit q = bit (3-q)
__device__ __forceinline__ int ring_perm_inv(int k) {
    if (k & 1) k ^= 8;   // CNOT(3,0)
    if (k & 2) k ^= 1;   // CNOT(2,3)
    if (k & 4) k ^= 2;   // CNOT(1,2)
    if (k & 8) k ^= 4;   // CNOT(0,1)
    return k;
}

__global__ void setup_kernel(const float* __restrict__ w) {
    __shared__ cplx sA[256], sB[256], sY[256];
    __shared__ cplx ug[4][2][2];
    int tid = threadIdx.x;
    int r = tid >> 4, c = tid & 15;

    for (int layer = 0; layer < 3; ++layer) {
        if (tid < 4) {
            int q = tid, off = 12*layer + 3*q;
            double t0 = w[off], t1 = w[off+1], t2 = w[off+2];
            double c0 = cos(0.5*t0), s0 = sin(0.5*t0);
            double cz = cos(0.5*t1), sz = sin(0.5*t1);
            double c2 = cos(0.5*t2), s2 = sin(0.5*t2);
            // B = Rz(t1) Ry(t0);  u = Ry(t2) B
            cplx B00 = { cz*c0, -sz*c0 }, B01 = { -cz*s0, sz*s0 };
            cplx B10 = { cz*s0,  sz*s0 }, B11 = {  cz*c0, sz*c0 };
            ug[q][0][0] = { c2*B00.re - s2*B10.re, c2*B00.im - s2*B10.im };
            ug[q][0][1] = { c2*B01.re - s2*B11.re, c2*B01.im - s2*B11.im };
            ug[q][1][0] = { s2*B00.re + c2*B10.re, s2*B00.im + c2*B10.im };
            ug[q][1][1] = { s2*B01.re + c2*B11.re, s2*B01.im + c2*B11.im };
        }
        __syncthreads();

        cplx y = { 1.0, 0.0 };
        #pragma unroll
        for (int q = 0; q < 4; ++q)
            y = cmul(y, ug[q][(r >> (3-q)) & 1][(c >> (3-q)) & 1]);

        if (layer == 0) {
            sA[tid] = y;  __syncthreads();
        } else {
            sY[tid] = y;  __syncthreads();
            cplx acc = { 0.0, 0.0 };
            #pragma unroll
            for (int k = 0; k < 16; ++k) {
                cplx p = cmul(sY[r*16 + k], sA[k*16 + c]);
                acc.re += p.re; acc.im += p.im;
            }
            sB[tid] = acc; __syncthreads();
            sA[tid] = sB[tid]; __syncthreads();
        }
        if (layer < 2) {  // U = ring @ U : row permutation
            cplx v = sA[ring_perm_inv(r)*16 + c];
            __syncthreads();
            sA[tid] = v;
            __syncthreads();
        }
    }

    // A[i][j] = Re( sum_k conj(U[k][i]) * U[15-k][j] )
    {
        int i = r, j = c;
        double are = 0.0;
        #pragma unroll
        for (int k = 0; k < 16; ++k) {
            cplx a = sA[k*16 + i], b = sA[(15-k)*16 + j];
            are += a.re*b.re + a.im*b.im;
        }
        g_coef[tid] = (j < i) ? 0.0f : (j == i ? (float)are : (float)(2.0*are));
    }
    for (int idx = tid; idx < BATCH*16; idx += 256) g_Q[idx] = 0.0f;
}

// ---------------------------------------------------------------------------
// Windows s=1..12 from a 128KB smem tile (half a row). Grid = BATCH*2, 256 thr.
// swizzle: phys(L) = L ^ ((L>>4)&30)
// ---------------------------------------------------------------------------
__global__ void __launch_bounds__(256, 1)
gram_main_kernel(const float* __restrict__ x) {
    extern __shared__ float sm[];          // 32768 tile + 256 coef
    float* sC = sm + 32768;
    int tid = threadIdx.x;
    int b = blockIdx.x >> 1, tile = blockIdx.x & 1;
    const float* src = x + (size_t)b * DIM + tile * 32768;

    sC[tid] = g_coef[tid];

    #pragma unroll 4
    for (int it = 0; it < 32; ++it) {
        int f = it*256 + tid;
        float4 v = *(const float4*)(src + (f << 2));
        int L = f << 2, m = (L >> 4) & 30;
        *(float2*)(sm + (L ^ m))       = make_float2(v.x, v.y);
        *(float2*)(sm + ((L+2) ^ m))   = make_float2(v.z, v.w);
    }
    __syncthreads();

    #pragma unroll 1
    for (int s = 1; s <= 12; ++s) {
        const int lr = 12 - s;            // stride = 1<<lr  (2048..1)

        float G[136];
        #pragma unroll
        for (int t = 0; t < 136; ++t) G[t] = 0.0f;

        #pragma unroll 2
        for (int k = 0; k < 8; ++k) {     // 2048 vectors / 256 threads
            int v = (k << 8) + tid;
            int a = v >> lr;
            int d = v - (a << lr);
            int base = (a << (lr + 4)) + d;
            float xv[16];
            #pragma unroll
            for (int i = 0; i < 16; ++i) {
                int L = base + (i << lr);
                xv[i] = sm[L ^ ((L >> 4) & 30)];
            }
            int t = 0;
            #pragma unroll
            for (int i = 0; i < 16; ++i)
                #pragma unroll
                for (int j = i; j < 16; ++j) { G[t] = fmaf(xv[i], xv[j], G[t]); ++t; }
        }

        float accv[4] = {0.f,0.f,0.f,0.f};
        float tr = 0.f;
        int t = 0;
        #pragma unroll
        for (int i = 0; i < 16; ++i) {
            tr += G[t];
            #pragma unroll
            for (int j = i; j < 16; ++j) {
                accv[t & 3] = fmaf(G[t], sC[i*16 + j], accv[t & 3]); ++t;
            }
        }
        float acc = (accv[0]+accv[1]) + (accv[2]+accv[3]);

        #pragma unroll
        for (int o = 16; o > 0; o >>= 1)
            acc += __shfl_xor_sync(0xffffffffu, acc, o);
        if (s == 1) {
            #pragma unroll
            for (int o = 16; o > 0; o >>= 1)
                tr += __shfl_xor_sync(0xffffffffu, tr, o);
        }
        if ((tid & 31) == 0) {
            atomicAdd(&g_Q[b*16 + s], acc);
            if (s == 1) atomicAdd(&g_Q[b*16 + 13], tr);
        }
    }
}

// ---------------------------------------------------------------------------
// Window s=0 (stride 4096): coalesced global. Grid = BATCH, 256 thr.
// ---------------------------------------------------------------------------
__global__ void __launch_bounds__(256, 1)
gram_s0_kernel(const float* __restrict__ x) {
    __shared__ float sC[256];
    int tid = threadIdx.x;
    int b = blockIdx.x;
    const float* src = x + (size_t)b * DIM;
    sC[tid] = g_coef[tid];
    __syncthreads();

    float G[136];
    #pragma unroll
    for (int t = 0; t < 136; ++t) G[t] = 0.0f;

    #pragma unroll 2
    for (int k = 0; k < 16; ++k) {
        int d = (k << 8) + tid;           // 0..4095
        float xv[16];
        #pragma unroll
        for (int i = 0; i < 16; ++i) xv[i] = src[i*4096 + d];
        int t = 0;
        #pragma unroll
        for (int i = 0; i < 16; ++i)
            #pragma unroll
            for (int j = i; j < 16; ++j) { G[t] = fmaf(xv[i], xv[j], G[t]); ++t; }
    }

    float accv[4] = {0.f,0.f,0.f,0.f};
    int t = 0;
    #pragma unroll
    for (int i = 0; i < 16; ++i)
        #pragma unroll
        for (int j = i; j < 16; ++j) {
            accv[t & 3] = fmaf(G[t], sC[i*16 + j], accv[t & 3]); ++t;
        }
    float acc = (accv[0]+accv[1]) + (accv[2]+accv[3]);

    #pragma unroll
    for (int o = 16; o > 0; o >>= 1)
        acc += __shfl_xor_sync(0xffffffffu, acc, o);
    if ((tid & 31) == 0) atomicAdd(&g_Q[b*16 + 0], acc);
}

// ---------------------------------------------------------------------------
// Finalize: out[b][s] = Q[b][s] / ||x_b||^2
// ---------------------------------------------------------------------------
__global__ void finalize_kernel(float* __restrict__ out) {
    int b = blockIdx.x;
    int s = threadIdx.x;                  // 0..12
    float inv = 1.0f / g_Q[b*16 + 13];
    out[b*NWIN + s] = g_Q[b*16 + s] * inv;
}

extern "C" void kernel_launch(void* const* d_in, const int* in_sizes, int n_in,
                              void* d_out, int out_size) {
    const float* x = (const float*)d_in[0];
    const float* w = (const float*)d_in[1];
    float* out = (float*)d_out;

    setup_kernel<<<1, 256>>>(w);

    size_t smem = (32768 + 256) * sizeof(float);
    cudaFuncSetAttribute(gram_main_kernel,
                         cudaFuncAttributeMaxDynamicSharedMemorySize, (int)smem);
    gram_main_kernel<<<BATCH * 2, 256, smem>>>(x);
    gram_s0_kernel<<<BATCH, 256>>>(x);
    finalize_kernel<<<BATCH, NWIN>>>(out);
}